// round 2
// baseline (speedup 1.0000x reference)
#include <cuda_runtime.h>
#include <cuda_bf16.h>
#include <math.h>

// DecodeSBP: per-keypoint argmax over sigmoid heatmaps.
// x: [1, 133, 512, 512] fp32.  out: [133,3] = (x*4, y*4, conf) or (-4,-4,-1).
// sigmoid monotonic -> argmax(sigmoid) == argmax; sigmoid applied only to the max.
//
// Split each keypoint into CHUNKS blocks for full-chip balance; each block emits
// a 64-bit key = (monotonic float bits << 32) | ~index, so a plain max gives the
// max value with the SMALLEST index on ties (matches jnp.argmax first-occurrence).
// Last finishing block reduces all partials and decodes.

#define KPTS   133
#define HW     (512 * 512)
#define W      512
#define SCALE  4.0f
#define CONF_THRESHOLD 0.8f

#define CHUNKS   16
#define NTHREADS 256
#define CHUNK_ELEMS (HW / CHUNKS)          // 16384
#define CHUNK_VEC   (CHUNK_ELEMS / 4)      // 4096 float4
#define ITERS       (CHUNK_VEC / NTHREADS) // 16
#define NBLOCKS     (KPTS * CHUNKS)        // 2128

__device__ unsigned long long g_partials[NBLOCKS];
__device__ unsigned int g_count = 0;

__device__ __forceinline__ unsigned int float_to_key(float f) {
    unsigned int u = __float_as_uint(f);
    // negative: flip all bits; positive: flip sign bit -> monotonic unsigned order
    return u ^ ((unsigned int)((int)u >> 31) | 0x80000000u);
}
__device__ __forceinline__ float key_to_float(unsigned int k) {
    unsigned int u = (k & 0x80000000u) ? (k ^ 0x80000000u) : ~k;
    return __uint_as_float(u);
}

__global__ __launch_bounds__(NTHREADS, 8)
void decode_sbp_kernel(const float* __restrict__ x, float* __restrict__ out) {
    const int chunk = blockIdx.x;
    const int k     = blockIdx.y;
    const int base_elem = chunk * CHUNK_ELEMS;
    const float4* __restrict__ p =
        reinterpret_cast<const float4*>(x + (size_t)k * HW + base_elem);

    const int tid = threadIdx.x;

    float best = -INFINITY;
    int bidx = 0;

    // Strictly increasing indices per thread -> strict '>' keeps first occurrence.
    #pragma unroll 8
    for (int i = 0; i < ITERS; i++) {
        const int j = i * NTHREADS + tid;
        float4 v = p[j];
        const int b = base_elem + (j << 2);
        if (v.x > best) { best = v.x; bidx = b;     }
        if (v.y > best) { best = v.y; bidx = b + 1; }
        if (v.z > best) { best = v.z; bidx = b + 2; }
        if (v.w > best) { best = v.w; bidx = b + 3; }
    }

    // Pack into one 64-bit max-reducible key.
    unsigned long long key =
        ((unsigned long long)float_to_key(best) << 32) | (unsigned int)(~bidx);

    #pragma unroll
    for (int off = 16; off > 0; off >>= 1) {
        unsigned long long o = __shfl_down_sync(0xFFFFFFFFu, key, off);
        if (o > key) key = o;
    }

    __shared__ unsigned long long s_key[NTHREADS / 32];
    __shared__ int s_last;
    const int lane = tid & 31;
    const int wid  = tid >> 5;
    if (lane == 0) s_key[wid] = key;
    __syncthreads();

    if (tid == 0) {
        #pragma unroll
        for (int w = 1; w < NTHREADS / 32; w++)
            if (s_key[w] > key) key = s_key[w];
        g_partials[k * CHUNKS + chunk] = key;
        __threadfence();
        unsigned int old = atomicAdd(&g_count, 1u);
        s_last = (old == NBLOCKS - 1) ? 1 : 0;
    }
    __syncthreads();

    if (s_last) {
        // Last block: reduce 16 partials per keypoint and decode.
        for (int kk = tid; kk < KPTS; kk += NTHREADS) {
            unsigned long long m = g_partials[kk * CHUNKS];
            #pragma unroll
            for (int c = 1; c < CHUNKS; c++) {
                unsigned long long v = g_partials[kk * CHUNKS + c];
                if (v > m) m = v;
            }
            const float mv  = key_to_float((unsigned int)(m >> 32));
            const int   idx = (int)~(unsigned int)(m & 0xFFFFFFFFu);
            const float conf = 1.0f / (1.0f + __expf(-mv));
            const bool valid = conf > CONF_THRESHOLD;
            const float yy = (float)(idx / W);
            const float xx = (float)(idx % W);
            out[kk * 3 + 0] = valid ? xx * SCALE : -SCALE;
            out[kk * 3 + 1] = valid ? yy * SCALE : -SCALE;
            out[kk * 3 + 2] = valid ? conf : -1.0f;
        }
        __syncthreads();
        if (tid == 0) g_count = 0;   // reset for next graph replay
    }
}

extern "C" void kernel_launch(void* const* d_in, const int* in_sizes, int n_in,
                              void* d_out, int out_size) {
    const float* x = (const float*)d_in[0];
    float* out = (float*)d_out;
    dim3 grid(CHUNKS, KPTS);
    decode_sbp_kernel<<<grid, NTHREADS>>>(x, out);
}

// round 3
// speedup vs baseline: 1.0010x; 1.0010x over previous
#include <cuda_runtime.h>
#include <cuda_bf16.h>
#include <math.h>

// DecodeSBP: per-keypoint argmax over sigmoid heatmaps.
// x: [1, 133, 512, 512] fp32.  out: [133,3] = (x*4, y*4, conf) or (-4,-4,-1).
// sigmoid monotonic -> argmax(sigmoid) == argmax; sigmoid applied only to the max.
//
// Flat-balanced: tensor split into 296 equal contiguous segments (one per CTA,
// single wave, 2 CTAs/SM on all 148 SMs). Each segment spans <=2 keypoints;
// per keypoint touched, the CTA block-reduces a 64-bit key
// (monotonic float bits << 32) | ~local_idx and atomicMax's into g_best[k].
// Max over keys == max value with smallest index (first-occurrence argmax).
// Last CTA decodes and resets state for graph replay.

#define KPTS   133
#define HW     (512 * 512)          // 262144 elems per keypoint
#define HW4    (HW / 4)             // 65536 float4 per keypoint
#define W      512
#define SCALE  4.0f
#define CONF_THRESHOLD 0.8f

#define NT     512
#define GRID   296
#define N4     (KPTS * HW4)                 // 8,716,288 float4 total
#define SEG    ((N4 + GRID - 1) / GRID)     // 29,448 float4 per segment

__device__ unsigned long long g_best[KPTS];   // zero-init == -inf key
__device__ unsigned int g_count = 0;

__device__ __forceinline__ unsigned int float_to_key(float f) {
    unsigned int u = __float_as_uint(f);
    return u ^ ((unsigned int)((int)u >> 31) | 0x80000000u);
}
__device__ __forceinline__ float key_to_float(unsigned int k) {
    unsigned int u = (k & 0x80000000u) ? (k ^ 0x80000000u) : ~k;
    return __uint_as_float(u);
}

// Reduce (best,bidx) across the block and atomicMax into g_best[k].
__device__ __forceinline__ void flush_kpt(float best, int bidx, int k,
                                          unsigned long long* s_key) {
    unsigned long long key =
        ((unsigned long long)float_to_key(best) << 32) | (unsigned int)(~bidx);
    #pragma unroll
    for (int off = 16; off > 0; off >>= 1) {
        unsigned long long o = __shfl_down_sync(0xFFFFFFFFu, key, off);
        if (o > key) key = o;
    }
    const int tid = threadIdx.x, lane = tid & 31, wid = tid >> 5;
    if (lane == 0) s_key[wid] = key;
    __syncthreads();
    if (tid == 0) {
        #pragma unroll
        for (int w = 1; w < NT / 32; w++)
            if (s_key[w] > key) key = s_key[w];
        atomicMax(&g_best[k], key);
    }
    __syncthreads();   // allow smem reuse by a second flush
}

// Scan float4 range [lo, hi) belonging to keypoint k; flush result.
__device__ __forceinline__ void scan_range(const float4* __restrict__ p4,
                                           int lo, int hi, int k,
                                           unsigned long long* s_key) {
    float best = -INFINITY;
    int bidx = 0;
    const int kbase = k << 18;   // k * HW
    // Indices strictly increasing per thread -> '>' keeps first occurrence.
    #pragma unroll 8
    for (int j = lo + threadIdx.x; j < hi; j += NT) {
        float4 v = p4[j];
        const int b = (j << 2) - kbase;   // local index within keypoint
        if (v.x > best) { best = v.x; bidx = b;     }
        if (v.y > best) { best = v.y; bidx = b + 1; }
        if (v.z > best) { best = v.z; bidx = b + 2; }
        if (v.w > best) { best = v.w; bidx = b + 3; }
    }
    flush_kpt(best, bidx, k, s_key);
}

__global__ __launch_bounds__(NT, 2)
void decode_sbp_kernel(const float* __restrict__ x, float* __restrict__ out) {
    const float4* __restrict__ p4 = reinterpret_cast<const float4*>(x);
    __shared__ unsigned long long s_key[NT / 32];
    __shared__ int s_last;

    const int s = blockIdx.x * SEG;
    const int e = min(s + SEG, N4);
    const int k0 = s >> 16;           // / HW4
    const int k1 = (e - 1) >> 16;

    if (k0 == k1) {
        scan_range(p4, s, e, k0, s_key);
    } else {
        const int bnd = k1 << 16;     // keypoint boundary in float4 units
        scan_range(p4, s, bnd, k0, s_key);
        scan_range(p4, bnd, e, k1, s_key);
    }

    if (threadIdx.x == 0) {
        __threadfence();
        unsigned int old = atomicAdd(&g_count, 1u);
        s_last = (old == GRID - 1) ? 1 : 0;
    }
    __syncthreads();

    if (s_last) {
        __threadfence();
        const int t = threadIdx.x;
        if (t < KPTS) {
            const unsigned long long m = g_best[t];
            const float mv  = key_to_float((unsigned int)(m >> 32));
            const int   idx = (int)~(unsigned int)(m & 0xFFFFFFFFu);
            const float conf = 1.0f / (1.0f + __expf(-mv));
            const bool valid = conf > CONF_THRESHOLD;
            const float yy = (float)(idx / W);
            const float xx = (float)(idx % W);
            out[t * 3 + 0] = valid ? xx * SCALE : -SCALE;
            out[t * 3 + 1] = valid ? yy * SCALE : -SCALE;
            out[t * 3 + 2] = valid ? conf : -1.0f;
            g_best[t] = 0ull;          // reset for next graph replay
        }
        if (t == 0) g_count = 0;
    }
}

extern "C" void kernel_launch(void* const* d_in, const int* in_sizes, int n_in,
                              void* d_out, int out_size) {
    const float* x = (const float*)d_in[0];
    float* out = (float*)d_out;
    decode_sbp_kernel<<<GRID, NT>>>(x, out);
}